// round 13
// baseline (speedup 1.0000x reference)
#include <cuda_runtime.h>
#include <cuda_bf16.h>
#include <cstdint>

// Problem constants
#define BB   256
#define TT   2048
#define IND  6
#define HID  64
#define GG   192          // 3*HID
#define DPK  64
#define NROWS (BB*TT)     // 524288
#define EPS  1e-5f
#define CH   2            // chains per GRU CTA
#define NBLK (TT/8)       // 256 gi blocks of 8 timesteps

typedef unsigned long long u64;

// ---------------- scratch (allocation-free: __device__ globals) -------------
// gi J-MAJOR: index = row*GG + gate*64 + j; produced INSIDE k_gru by gi warps.
// biases pre-folded: r,z gates carry b_ih+b_hh; n gate carries b_ih only.
__device__ float g_gi[(size_t)NROWS * GG];       // 402 MB
__device__ float g_hseq[(size_t)NROWS * HID];    // 128 MB : GRU hidden states [b][t][j]

// ---------------- packed f32x2 helpers --------------------------------------
__device__ __forceinline__ u64 fma2(u64 a, u64 b, u64 c) {
    u64 d;
    asm("fma.rn.f32x2 %0, %1, %2, %3;" : "=l"(d) : "l"(a), "l"(b), "l"(c));
    return d;
}
__device__ __forceinline__ u64 add2(u64 a, u64 b) {
    u64 d;
    asm("add.rn.f32x2 %0, %1, %2;" : "=l"(d) : "l"(a), "l"(b));
    return d;
}
__device__ __forceinline__ u64 pack2(float a, float b) {
    u64 r;
    asm("mov.b64 %0, {%1,%2};" : "=l"(r) : "f"(a), "f"(b));
    return r;
}
__device__ __forceinline__ float psum(u64 a) {
    return __uint_as_float((unsigned)(a & 0xffffffffull)) +
           __uint_as_float((unsigned)(a >> 32));
}
// plain (coherent) global load — rec must NOT use __ldg for gi: the RO/NC path
// may serve stale data for values written during this kernel by gi warps.
__device__ __forceinline__ float ldg_plain(const float* p) {
    float v;
    asm volatile("ld.global.f32 %0, [%1];" : "=f"(v) : "l"(p));
    return v;
}
__device__ __forceinline__ unsigned ld_acquire_u32(const unsigned* p) {
    unsigned v;
    asm volatile("ld.acquire.cta.u32 %0, [%1];" : "=r"(v) : "l"(p) : "memory");
    return v;
}
__device__ __forceinline__ void st_release_u32(unsigned* p, unsigned v) {
    asm volatile("st.release.cta.u32 [%0], %1;" :: "l"(p), "r"(v) : "memory");
}

// EXACT-path activations (validated rel_err ~2.5e-7 over the full recurrence).
// tanh.approx is banned anywhere upstream of the recurrence (R5: per-step
// errors compound to ~0.15). GELU stays erf-exact for the same reason.
__device__ __forceinline__ float sigmoidf_(float x) {
    return __fdividef(1.f, 1.f + __expf(-x));
}
__device__ __forceinline__ float tanhf_(float x) {
    float e = __expf(2.f * x);
    return 1.f - __fdividef(2.f, e + 1.f);   // safe at e->inf (->1) and e->0 (->-1)
}

// ================== K2: FUSED inproj + gi-producer + GRU recurrence =========
// grid = 128 CTAs, block = 256 threads, 2 chains:
//   tid   0- 63 : producer, chain 0  (warps 0,1 -- LOW wid = low priority)
//   tid  64-127 : producer, chain 1  (warps 2,3)
//   tid 128-191 : recurrence, chain 0 (warps 4,5 -- HIGH wid = priority)
//   tid 192-255 : recurrence, chain 1 (warps 6,7)
// SMSP s hosts warp s (producer) + warp s+4 (rec): producers have NO per-step
// barrier coupling to rec, so they stream work into rec's exposed-latency
// windows (R12 validated this; gru hit ~705cyc/step = issue-saturated).
//
// Producer warps now ALSO compute the input projection (R13): per 8-step
// block, warp wg computes x for rows 4wg..4wg+3 (k_inproj's exact lane
// layout: 12 FMA + shfl-LN + erf GELU) into xsh, with drug_ce double-
// buffered in dsh. Then the dot phase (thread j owns W_ih rows {j,64+j,
// 128+j}, 96 u64 regs) produces gi for 8 steps, STG coalesced, publishes
// progress via st.release flag. Deletes the k_inproj kernel AND the 256MB
// g_x round-trip.
// rec warps: EXACT R8 inner loop (full 64-wide dots from 16-slot smem h
// ring, 96 u64 weight regs, coalesced float4 h flush every 8 steps), gi via
// coherent ld.global, ld.acquire flag gate every 8 steps.
__global__ void __launch_bounds__(256, 1) k_gru(
    const float* __restrict__ drug,
    const float* __restrict__ w1,
    const float* __restrict__ b1,
    const float* __restrict__ ln1g,
    const float* __restrict__ ln1b,
    const float* __restrict__ Wih,
    const float* __restrict__ bih,
    const float* __restrict__ Whh,
    const float* __restrict__ bhh)
{
    const int tid   = threadIdx.x;
    const int role  = tid >> 7;            // 0 = producer, 1 = recurrence
    const int chain = (tid >> 6) & 1;
    const int j     = tid & 63;
    const size_t brow = (size_t)blockIdx.x * CH + chain;

    __shared__ __align__(16) float ring[16][CH][64];  // 8 KB h history
    __shared__ __align__(16) float xsh[CH][8][64];    // 4 KB x staging
    __shared__ float dsh[CH][2][8][IND];              // drug double buffer
    __shared__ unsigned flags[CH];                    // gi blocks completed

    if (tid < CH) flags[tid] = 0;
    __syncthreads();                                  // flags visible to all

    if (role == 0) {
        // ================= producer (inproj + gi) =================
        const unsigned gibar = 3 + chain;             // 64-thread named barrier
        const int wg   = j >> 5;                      // producer warp in chain
        const int lane = j & 31;

        // gi dot weights: thread j owns W_ih rows {j, 64+j, 128+j}
        u64 wr[32], wz[32], wn[32];
        {
            const u64* rrow = (const u64*)(Wih + (size_t)j * HID);
            const u64* zrow = (const u64*)(Wih + (size_t)(64 + j) * HID);
            const u64* nrow = (const u64*)(Wih + (size_t)(128 + j) * HID);
#pragma unroll
            for (int k = 0; k < 32; ++k) { wr[k] = rrow[k]; wz[k] = zrow[k]; wn[k] = nrow[k]; }
        }
        const float bir = bih[j]       + bhh[j];
        const float biz = bih[64 + j]  + bhh[64 + j];
        const float bin = bih[128 + j];

        // inproj params (compute layout: lane owns cols lane, lane+32)
        float w1r[2 * IND];
#pragma unroll
        for (int i = 0; i < IND; ++i) {
            w1r[i]       = w1[i * HID + lane];
            w1r[IND + i] = w1[i * HID + lane + 32];
        }
        const float b1v0 = b1[lane],   b1v1 = b1[lane + 32];
        const float g1v0 = ln1g[lane], g1v1 = ln1g[lane + 32];
        const float e1v0 = ln1b[lane], e1v1 = ln1b[lane + 32];

        const float* dbase = drug + brow * (size_t)TT * IND;
        float*       gout  = g_gi + brow * (size_t)TT * GG;

        // prime drug block 0
        if (j < 8 * IND)
            dsh[chain][0][j / IND][j % IND] = __ldg(dbase + j);

#pragma unroll 1
        for (int b = 0; b < NBLK; ++b) {
            asm volatile("bar.sync %0, 64;" :: "r"(gibar) : "memory");
            if (j == 0 && b) st_release_u32(&flags[chain], (unsigned)b);
            const int par = b & 1;

            // ---- phase A: input proj + LN + exact GELU, 4 rows per warp ----
#pragma unroll
            for (int rr = 0; rr < 4; ++rr) {
                const int r = wg * 4 + rr;
                float v0 = b1v0, v1 = b1v1;
#pragma unroll
                for (int i = 0; i < IND; ++i) {
                    const float ci = dsh[chain][par][r][i];   // LDS broadcast
                    v0 = fmaf(ci, w1r[i],       v0);
                    v1 = fmaf(ci, w1r[IND + i], v1);
                }
                float s = v0 + v1;
#pragma unroll
                for (int o = 16; o; o >>= 1) s += __shfl_xor_sync(0xffffffffu, s, o);
                const float m = s * (1.f / 64.f);
                const float d0 = v0 - m, d1 = v1 - m;
                float q = d0 * d0 + d1 * d1;
#pragma unroll
                for (int o = 16; o; o >>= 1) q += __shfl_xor_sync(0xffffffffu, q, o);
                const float rs = rsqrtf(q * (1.f / 64.f) + EPS);
                const float y0 = d0 * rs * g1v0 + e1v0;
                const float y1 = d1 * rs * g1v1 + e1v1;
                const float kc = 0.70710678118654752f;
                xsh[chain][r][lane]      = 0.5f * y0 * (1.f + erff(y0 * kc));
                xsh[chain][r][lane + 32] = 0.5f * y1 * (1.f + erff(y1 * kc));
            }
            asm volatile("bar.sync %0, 64;" :: "r"(gibar) : "memory");

            // ---- phase C: prefetch drug block b+1 into the other buffer ----
            if (b + 1 < NBLK && j < 8 * IND)
                dsh[chain][par ^ 1][j / IND][j % IND] =
                    __ldg(dbase + (size_t)(b + 1) * 8 * IND + j);

            // ---- phase D: gi dots for 8 steps ----
#pragma unroll
            for (int r = 0; r < 8; ++r) {
                const ulonglong2* xv = (const ulonglong2*)xsh[chain][r];
                u64 ar0 = 0, ar1 = 0, az0 = 0, az1 = 0, an0 = 0, an1 = 0;
#pragma unroll
                for (int kk = 0; kk < 16; ++kk) {
                    const ulonglong2 p = xv[kk];        // LDS.128 broadcast
                    ar0 = fma2(wr[2 * kk],     p.x, ar0);
                    az0 = fma2(wz[2 * kk],     p.x, az0);
                    an0 = fma2(wn[2 * kk],     p.x, an0);
                    ar1 = fma2(wr[2 * kk + 1], p.y, ar1);
                    az1 = fma2(wz[2 * kk + 1], p.y, az1);
                    an1 = fma2(wn[2 * kk + 1], p.y, an1);
                }
                float* d = gout + (size_t)(b * 8 + r) * GG + j;
                d[0]   = psum(add2(ar0, ar1)) + bir;
                d[64]  = psum(add2(az0, az1)) + biz;
                d[128] = psum(add2(an0, an1)) + bin;
            }
        }
        asm volatile("bar.sync %0, 64;" :: "r"(gibar) : "memory");
        if (j == 0) st_release_u32(&flags[chain], (unsigned)NBLK);

    } else {
        // ================= recurrence (R8 inner loop) =================
        const unsigned barid = 1 + chain;             // 64-thread named barrier
        u64 wr[32], wz[32], wn[32];
        {
            const u64* rrow = (const u64*)(Whh + (size_t)j * HID);
            const u64* zrow = (const u64*)(Whh + (size_t)(64 + j) * HID);
            const u64* nrow = (const u64*)(Whh + (size_t)(128 + j) * HID);
#pragma unroll
            for (int k = 0; k < 32; ++k) { wr[k] = rrow[k]; wz[k] = zrow[k]; wn[k] = nrow[k]; }
        }
        const float bhn = bhh[128 + j];

        ring[15][chain][j] = 0.f;                     // h_{-1} = 0
        float hprev = 0.f;

        const float* gib = g_gi + brow * (size_t)TT * GG + j;
        float* hbase = g_hseq + brow * (size_t)TT * HID;

        // wait for gi blocks 0,1 then prime the 4-step gi buffer
        while (ld_acquire_u32(&flags[chain]) < 2u) __nanosleep(128);
        float cr0 = ldg_plain(gib + 0 * GG), cz0 = ldg_plain(gib + 0 * GG + 64), cn0 = ldg_plain(gib + 0 * GG + 128);
        float cr1 = ldg_plain(gib + 1 * GG), cz1 = ldg_plain(gib + 1 * GG + 64), cn1 = ldg_plain(gib + 1 * GG + 128);
        float cr2 = ldg_plain(gib + 2 * GG), cz2 = ldg_plain(gib + 2 * GG + 64), cn2 = ldg_plain(gib + 2 * GG + 128);
        float cr3 = ldg_plain(gib + 3 * GG), cz3 = ldg_plain(gib + 3 * GG + 64), cn3 = ldg_plain(gib + 3 * GG + 128);

        asm volatile("bar.sync %0, 64;" :: "r"(barid) : "memory");

        auto step = [&](const int t, const float ir, const float iz, const float inn) {
            const ulonglong2* hv = (const ulonglong2*)ring[(t + 15) & 15][chain];
            u64 ar = 0, az = 0, an = 0;
#pragma unroll
            for (int kk = 0; kk < 16; ++kk) {          // full 64-wide dot
                const ulonglong2 p = hv[kk];           // LDS.128 broadcast
                ar = fma2(wr[2 * kk],     p.x, ar);
                az = fma2(wz[2 * kk],     p.x, az);
                an = fma2(wn[2 * kk],     p.x, an);
                ar = fma2(wr[2 * kk + 1], p.y, ar);
                az = fma2(wz[2 * kk + 1], p.y, az);
                an = fma2(wn[2 * kk + 1], p.y, an);
            }
            const float r = sigmoidf_(ir + psum(ar));  // biases pre-folded in gi
            const float z = sigmoidf_(iz + psum(az));
            const float n = tanhf_(inn + r * (psum(an) + bhn));
            const float hnew = fmaf(z, hprev - n, n);  // (1-z)*n + z*h
            ring[t & 15][chain][j] = hnew;
            hprev = hnew;
            asm volatile("bar.sync %0, 64;" :: "r"(barid) : "memory");
        };

#pragma unroll 1
        for (int blk = 0; blk < TT / 4; ++blk) {
            const int t0 = blk * 4;
            if ((blk & 1) == 0 && blk) {
                // entering t0=8m: prefetch will reach gi step 8m+11 (block m+1)
                const unsigned need = (unsigned)min((blk >> 1) + 2, NBLK);
                if (ld_acquire_u32(&flags[chain]) < need)
                    while (ld_acquire_u32(&flags[chain]) < need) __nanosleep(128);
            }
            const bool pf = (blk + 1 < TT / 4);
            const float* p = gib + (size_t)(t0 + 4) * GG;

            { const float ir = cr0, iz = cz0, inn = cn0;
              if (pf) { cr0 = ldg_plain(p + 0 * GG); cz0 = ldg_plain(p + 0 * GG + 64); cn0 = ldg_plain(p + 0 * GG + 128); }
              step(t0 + 0, ir, iz, inn); }
            { const float ir = cr1, iz = cz1, inn = cn1;
              if (pf) { cr1 = ldg_plain(p + 1 * GG); cz1 = ldg_plain(p + 1 * GG + 64); cn1 = ldg_plain(p + 1 * GG + 128); }
              step(t0 + 1, ir, iz, inn); }
            { const float ir = cr2, iz = cz2, inn = cn2;
              if (pf) { cr2 = ldg_plain(p + 2 * GG); cz2 = ldg_plain(p + 2 * GG + 64); cn2 = ldg_plain(p + 2 * GG + 128); }
              step(t0 + 2, ir, iz, inn); }
            { const float ir = cr3, iz = cz3, inn = cn3;
              if (pf) { cr3 = ldg_plain(p + 3 * GG); cz3 = ldg_plain(p + 3 * GG + 64); cn3 = ldg_plain(p + 3 * GG + 128); }
              step(t0 + 3, ir, iz, inn); }

            if (blk & 1) {
                // flush steps tb..tb+7 (ring slots (tb&15)..+7), coalesced.
                // Safe: these slots are next overwritten >= 9 barriers later.
                const int tb = t0 - 4;               // multiple of 8
                const int sb = tb & 15;              // 0 or 8
#pragma unroll
                for (int q = 0; q < 2; ++q) {
                    const int idx  = q * 64 + j;     // 0..127
                    const int toff = idx >> 4;       // 0..7
                    const int jq   = idx & 15;       // float4 index within row
                    const float4 v = ((const float4*)ring[sb + toff][chain])[jq];
                    ((float4*)(hbase + (size_t)(tb + toff) * HID))[jq] = v;
                }
            }
        }
    }
}

// ================== K3: out proj + LN =======================================
// 256 threads / 8 warps; w2 packed in smem [k2][64] (conflict-free LDS.64);
// each warp processes 4 rows per iteration, SOFTWARE-PIPELINED: next 4 rows'
// LDG.64s issue before the fma loop, so global latency is hidden (R12 ncu:
// issue 42.8% -> loop-head LDG stalls were exposed).
__global__ void __launch_bounds__(256) k_outproj(const float* __restrict__ w2,
                                                 const float* __restrict__ b2,
                                                 const float* __restrict__ g2,
                                                 const float* __restrict__ bb2,
                                                 float* __restrict__ out)
{
    const int tid  = threadIdx.x;
    const int wid  = tid >> 5;
    const int lane = tid & 31;
    const int j0 = lane, j1 = lane + 32;

    __shared__ __align__(16) u64   w2p[32][64];     // 16 KB
    __shared__ __align__(16) float hst[8][4][64];   // 8 KB, per-warp staging

    for (int idx = tid; idx < 32 * 64; idx += 256) {
        const int k2 = idx >> 6, jj = idx & 63;
        w2p[k2][jj] = pack2(w2[(size_t)(2 * k2) * DPK + jj],
                            w2[(size_t)(2 * k2 + 1) * DPK + jj]);
    }
    __syncthreads();

    const float bo0 = b2[j0], bo1 = b2[j1];
    const float lg0 = g2[j0], lg1 = g2[j1];
    const float lb0 = bb2[j0], lb1 = bb2[j1];

    const size_t stride = (size_t)gridDim.x * 32;
    size_t base = (size_t)blockIdx.x * 32 + wid * 4;

    // prime: load first 4 rows into registers
    float2 p0, p1, p2, p3;
    if (base < (size_t)NROWS) {
        p0 = ((const float2*)(g_hseq + (base + 0) * HID))[lane];
        p1 = ((const float2*)(g_hseq + (base + 1) * HID))[lane];
        p2 = ((const float2*)(g_hseq + (base + 2) * HID))[lane];
        p3 = ((const float2*)(g_hseq + (base + 3) * HID))[lane];
    }

    for (; base < (size_t)NROWS; base += stride) {
        ((float2*)hst[wid][0])[lane] = p0;
        ((float2*)hst[wid][1])[lane] = p1;
        ((float2*)hst[wid][2])[lane] = p2;
        ((float2*)hst[wid][3])[lane] = p3;
        __syncwarp();

        // prefetch next iteration's rows (latency hidden by the fma loop)
        const size_t nb = base + stride;
        if (nb < (size_t)NROWS) {
            p0 = ((const float2*)(g_hseq + (nb + 0) * HID))[lane];
            p1 = ((const float2*)(g_hseq + (nb + 1) * HID))[lane];
            p2 = ((const float2*)(g_hseq + (nb + 2) * HID))[lane];
            p3 = ((const float2*)(g_hseq + (nb + 3) * HID))[lane];
        }

        const u64* hA = (const u64*)hst[wid][0];
        const u64* hB = (const u64*)hst[wid][1];
        const u64* hC = (const u64*)hst[wid][2];
        const u64* hD = (const u64*)hst[wid][3];
        u64 aA0 = 0, aA1 = 0, aB0 = 0, aB1 = 0;
        u64 aC0 = 0, aC1 = 0, aD0 = 0, aD1 = 0;
#pragma unroll
        for (int k2 = 0; k2 < 32; ++k2) {
            const u64 w0 = w2p[k2][j0];
            const u64 w1v = w2p[k2][j1];
            const u64 pA = hA[k2];
            const u64 pB = hB[k2];
            const u64 pC = hC[k2];
            const u64 pD = hD[k2];
            aA0 = fma2(w0, pA, aA0);  aA1 = fma2(w1v, pA, aA1);
            aB0 = fma2(w0, pB, aB0);  aB1 = fma2(w1v, pB, aB1);
            aC0 = fma2(w0, pC, aC0);  aC1 = fma2(w1v, pC, aC1);
            aD0 = fma2(w0, pD, aD0);  aD1 = fma2(w1v, pD, aD1);
        }

        u64 acc0[4] = {aA0, aB0, aC0, aD0};
        u64 acc1[4] = {aA1, aB1, aC1, aD1};
#pragma unroll
        for (int rr = 0; rr < 4; ++rr) {
            float o0 = psum(acc0[rr]) + bo0;
            float o1 = psum(acc1[rr]) + bo1;
            float s = o0 + o1;
#pragma unroll
            for (int o = 16; o; o >>= 1) s += __shfl_xor_sync(0xffffffffu, s, o);
            const float m = s * (1.f / 64.f);
            const float d0 = o0 - m, d1 = o1 - m;
            float q = d0 * d0 + d1 * d1;
#pragma unroll
            for (int o = 16; o; o >>= 1) q += __shfl_xor_sync(0xffffffffu, q, o);
            const float rs = rsqrtf(q * (1.f / 64.f) + EPS);
            const size_t row = base + rr;
            out[row * DPK + j0] = d0 * rs * lg0 + lb0;
            out[row * DPK + j1] = d1 * rs * lg1 + lb1;
        }
        __syncwarp();   // hst slot reused next iteration
    }
}

// ================== launcher =================================================
extern "C" void kernel_launch(void* const* d_in, const int* in_sizes, int n_in,
                              void* d_out, int out_size)
{
    const float* drug = (const float*)d_in[0];
    const float* w1   = (const float*)d_in[1];
    const float* b1   = (const float*)d_in[2];
    const float* ln1g = (const float*)d_in[3];
    const float* ln1b = (const float*)d_in[4];
    const float* Wih  = (const float*)d_in[5];
    const float* bih  = (const float*)d_in[6];
    const float* Whh  = (const float*)d_in[7];
    const float* bhh  = (const float*)d_in[8];
    const float* w2   = (const float*)d_in[9];
    const float* b2   = (const float*)d_in[10];
    const float* ln2g = (const float*)d_in[11];
    const float* ln2b = (const float*)d_in[12];
    float* out = (float*)d_out;

    k_gru<<<BB / CH, 256>>>(drug, w1, b1, ln1g, ln1b, Wih, bih, Whh, bhh);
    k_outproj<<<2048, 256>>>(w2, b2, ln2g, ln2b, out);
}

// round 14
// speedup vs baseline: 1.2675x; 1.2675x over previous
#include <cuda_runtime.h>
#include <cuda_bf16.h>
#include <cstdint>

// Problem constants
#define BB   256
#define TT   2048
#define IND  6
#define HID  64
#define GG   192          // 3*HID
#define DPK  64
#define NROWS (BB*TT)     // 524288
#define EPS  1e-5f
#define CH   2            // chains per GRU CTA
#define NBLK (TT/8)       // 256 gi blocks of 8 timesteps

typedef unsigned long long u64;

// ---------------- scratch (allocation-free: __device__ globals) -------------
__device__ float g_x[(size_t)NROWS * HID];       // 128 MB : post input-proj activations
// gi J-MAJOR: index = row*GG + gate*64 + j; produced INSIDE k_gru by gi warps.
// biases pre-folded: r,z gates carry b_ih+b_hh; n gate carries b_ih only.
__device__ float g_gi[(size_t)NROWS * GG];       // 402 MB
__device__ float g_hseq[(size_t)NROWS * HID];    // 128 MB : GRU hidden states [b][t][j]

// ---------------- packed f32x2 helpers --------------------------------------
__device__ __forceinline__ u64 fma2(u64 a, u64 b, u64 c) {
    u64 d;
    asm("fma.rn.f32x2 %0, %1, %2, %3;" : "=l"(d) : "l"(a), "l"(b), "l"(c));
    return d;
}
__device__ __forceinline__ u64 add2(u64 a, u64 b) {
    u64 d;
    asm("add.rn.f32x2 %0, %1, %2;" : "=l"(d) : "l"(a), "l"(b));
    return d;
}
__device__ __forceinline__ u64 pack2(float a, float b) {
    u64 r;
    asm("mov.b64 %0, {%1,%2};" : "=l"(r) : "f"(a), "f"(b));
    return r;
}
__device__ __forceinline__ float psum(u64 a) {
    return __uint_as_float((unsigned)(a & 0xffffffffull)) +
           __uint_as_float((unsigned)(a >> 32));
}
// plain (coherent) global load — rec must NOT use __ldg for gi: the RO/NC path
// may serve stale data for values written during this kernel by gi warps.
__device__ __forceinline__ float ldg_plain(const float* p) {
    float v;
    asm volatile("ld.global.f32 %0, [%1];" : "=f"(v) : "l"(p));
    return v;
}
__device__ __forceinline__ unsigned ld_acquire_u32(const unsigned* p) {
    unsigned v;
    asm volatile("ld.acquire.cta.u32 %0, [%1];" : "=r"(v) : "l"(p) : "memory");
    return v;
}
__device__ __forceinline__ void st_release_u32(unsigned* p, unsigned v) {
    asm volatile("st.release.cta.u32 [%0], %1;" :: "l"(p), "r"(v) : "memory");
}

// EXACT-path activations (validated rel_err ~2.5e-7 over the full recurrence).
// tanh.approx is banned anywhere upstream of the recurrence (R5: per-step
// errors compound to ~0.15). GELU stays erf-exact for the same reason.
__device__ __forceinline__ float sigmoidf_(float x) {
    return __fdividef(1.f, 1.f + __expf(-x));
}
__device__ __forceinline__ float tanhf_(float x) {
    float e = __expf(2.f * x);
    return 1.f - __fdividef(2.f, e + 1.f);   // safe at e->inf (->1) and e->0 (->-1)
}

// ================== K1a: input proj + LN + exact GELU ======================
// one warp per (b,t) row; each lane owns output cols lane, lane+32.
// 91us @ 77% issue (erff-bound) -- kept as a standalone kernel: R13 proved
// fusing it into the gi producers overruns the rec pacer (erff ~40 instrs).
__global__ void k_inproj(const float* __restrict__ ce,
                         const float* __restrict__ w1,
                         const float* __restrict__ b1,
                         const float* __restrict__ g1,
                         const float* __restrict__ bb1)
{
    const int wid  = threadIdx.x >> 5;
    const int lane = threadIdx.x & 31;
    const size_t row = (size_t)blockIdx.x * 8 + wid;   // grid = NROWS/8

    const float* c = ce + row * IND;
    float v0 = b1[lane], v1 = b1[lane + 32];
#pragma unroll
    for (int i = 0; i < IND; ++i) {
        float ci = __ldg(c + i);
        v0 = fmaf(ci, w1[i * HID + lane],      v0);
        v1 = fmaf(ci, w1[i * HID + lane + 32], v1);
    }
    float s = v0 + v1;
#pragma unroll
    for (int o = 16; o; o >>= 1) s += __shfl_xor_sync(0xffffffffu, s, o);
    const float m = s * (1.f / 64.f);
    const float d0 = v0 - m, d1 = v1 - m;
    float q = d0 * d0 + d1 * d1;
#pragma unroll
    for (int o = 16; o; o >>= 1) q += __shfl_xor_sync(0xffffffffu, q, o);
    const float rs = rsqrtf(q * (1.f / 64.f) + EPS);
    const float y0 = d0 * rs * g1[lane]      + bb1[lane];
    const float y1 = d1 * rs * g1[lane + 32] + bb1[lane + 32];
    const float k = 0.70710678118654752f;
    g_x[row * HID + lane]      = 0.5f * y0 * (1.f + erff(y0 * k));
    g_x[row * HID + lane + 32] = 0.5f * y1 * (1.f + erff(y1 * k));
}

// ================== K2: FUSED gi-producer + GRU recurrence (R12) ============
// grid = 128 CTAs, block = 256 threads, 2 chains:
//   tid   0- 63 : gi producer, chain 0  (warps 0,1 -- LOW wid = low priority)
//   tid  64-127 : gi producer, chain 1  (warps 2,3)
//   tid 128-191 : recurrence,  chain 0  (warps 4,5 -- HIGH wid = priority)
//   tid 192-255 : recurrence,  chain 1  (warps 6,7)
// SMSP s hosts warp s (gi) + warp s+4 (rec): the gi warp has NO per-step
// barrier, so it streams fma2 into the rec warp's exposed-latency windows.
// Measured (R12): gru ~705cyc/step = rec(410)+gi(330) issue-saturated.
__global__ void __launch_bounds__(256, 1) k_gru(const float* __restrict__ Wih,
                                                const float* __restrict__ bih,
                                                const float* __restrict__ Whh,
                                                const float* __restrict__ bhh)
{
    const int tid   = threadIdx.x;
    const int role  = tid >> 7;            // 0 = gi producer, 1 = recurrence
    const int chain = (tid >> 6) & 1;
    const int j     = tid & 63;
    const size_t brow = (size_t)blockIdx.x * CH + chain;

    __shared__ __align__(16) float ring[16][CH][64];  // 8 KB h history
    __shared__ __align__(16) float xsh[CH][8][64];    // 4 KB x staging (gi)
    __shared__ unsigned flags[CH];                    // gi blocks completed

    if (tid < CH) flags[tid] = 0;
    __syncthreads();                                  // flags visible to all

    if (role == 0) {
        // ================= gi producer =================
        const unsigned gibar = 3 + chain;             // 64-thread named barrier
        u64 wr[32], wz[32], wn[32];
        {
            const u64* rrow = (const u64*)(Wih + (size_t)j * HID);
            const u64* zrow = (const u64*)(Wih + (size_t)(64 + j) * HID);
            const u64* nrow = (const u64*)(Wih + (size_t)(128 + j) * HID);
#pragma unroll
            for (int k = 0; k < 32; ++k) { wr[k] = rrow[k]; wz[k] = zrow[k]; wn[k] = nrow[k]; }
        }
        const float bir = bih[j]       + bhh[j];
        const float biz = bih[64 + j]  + bhh[64 + j];
        const float bin = bih[128 + j];

        const float* xb   = g_x  + brow * (size_t)TT * HID;
        float*       gout = g_gi + brow * (size_t)TT * GG;

        float xr[8];
#pragma unroll
        for (int r = 0; r < 8; ++r) xr[r] = __ldg(xb + (size_t)r * HID + j);

#pragma unroll 1
        for (int b = 0; b < NBLK; ++b) {
            asm volatile("bar.sync %0, 64;" :: "r"(gibar) : "memory");
            if (j == 0 && b) st_release_u32(&flags[chain], (unsigned)b);
#pragma unroll
            for (int r = 0; r < 8; ++r) xsh[chain][r][j] = xr[r];
            asm volatile("bar.sync %0, 64;" :: "r"(gibar) : "memory");
            if (b + 1 < NBLK) {
                const float* xn = xb + (size_t)(b + 1) * 8 * HID + j;
#pragma unroll
                for (int r = 0; r < 8; ++r) xr[r] = __ldg(xn + (size_t)r * HID);
            }
#pragma unroll
            for (int r = 0; r < 8; ++r) {
                const ulonglong2* xv = (const ulonglong2*)xsh[chain][r];
                u64 ar0 = 0, ar1 = 0, az0 = 0, az1 = 0, an0 = 0, an1 = 0;
#pragma unroll
                for (int kk = 0; kk < 16; ++kk) {
                    const ulonglong2 p = xv[kk];        // LDS.128 broadcast
                    ar0 = fma2(wr[2 * kk],     p.x, ar0);
                    az0 = fma2(wz[2 * kk],     p.x, az0);
                    an0 = fma2(wn[2 * kk],     p.x, an0);
                    ar1 = fma2(wr[2 * kk + 1], p.y, ar1);
                    az1 = fma2(wz[2 * kk + 1], p.y, az1);
                    an1 = fma2(wn[2 * kk + 1], p.y, an1);
                }
                float* d = gout + (size_t)(b * 8 + r) * GG + j;
                d[0]   = psum(add2(ar0, ar1)) + bir;
                d[64]  = psum(add2(az0, az1)) + biz;
                d[128] = psum(add2(an0, an1)) + bin;
            }
        }
        asm volatile("bar.sync %0, 64;" :: "r"(gibar) : "memory");
        if (j == 0) st_release_u32(&flags[chain], (unsigned)NBLK);

    } else {
        // ================= recurrence (R8 inner loop) =================
        const unsigned barid = 1 + chain;             // 64-thread named barrier
        u64 wr[32], wz[32], wn[32];
        {
            const u64* rrow = (const u64*)(Whh + (size_t)j * HID);
            const u64* zrow = (const u64*)(Whh + (size_t)(64 + j) * HID);
            const u64* nrow = (const u64*)(Whh + (size_t)(128 + j) * HID);
#pragma unroll
            for (int k = 0; k < 32; ++k) { wr[k] = rrow[k]; wz[k] = zrow[k]; wn[k] = nrow[k]; }
        }
        const float bhn = bhh[128 + j];

        ring[15][chain][j] = 0.f;                     // h_{-1} = 0
        float hprev = 0.f;

        const float* gib = g_gi + brow * (size_t)TT * GG + j;
        float* hbase = g_hseq + brow * (size_t)TT * HID;

        // wait for gi blocks 0,1 then prime the 4-step gi buffer
        while (ld_acquire_u32(&flags[chain]) < 2u) __nanosleep(128);
        float cr0 = ldg_plain(gib + 0 * GG), cz0 = ldg_plain(gib + 0 * GG + 64), cn0 = ldg_plain(gib + 0 * GG + 128);
        float cr1 = ldg_plain(gib + 1 * GG), cz1 = ldg_plain(gib + 1 * GG + 64), cn1 = ldg_plain(gib + 1 * GG + 128);
        float cr2 = ldg_plain(gib + 2 * GG), cz2 = ldg_plain(gib + 2 * GG + 64), cn2 = ldg_plain(gib + 2 * GG + 128);
        float cr3 = ldg_plain(gib + 3 * GG), cz3 = ldg_plain(gib + 3 * GG + 64), cn3 = ldg_plain(gib + 3 * GG + 128);

        asm volatile("bar.sync %0, 64;" :: "r"(barid) : "memory");

        auto step = [&](const int t, const float ir, const float iz, const float inn) {
            const ulonglong2* hv = (const ulonglong2*)ring[(t + 15) & 15][chain];
            u64 ar = 0, az = 0, an = 0;
#pragma unroll
            for (int kk = 0; kk < 16; ++kk) {          // full 64-wide dot
                const ulonglong2 p = hv[kk];           // LDS.128 broadcast
                ar = fma2(wr[2 * kk],     p.x, ar);
                az = fma2(wz[2 * kk],     p.x, az);
                an = fma2(wn[2 * kk],     p.x, an);
                ar = fma2(wr[2 * kk + 1], p.y, ar);
                az = fma2(wz[2 * kk + 1], p.y, az);
                an = fma2(wn[2 * kk + 1], p.y, an);
            }
            const float r = sigmoidf_(ir + psum(ar));  // biases pre-folded in gi
            const float z = sigmoidf_(iz + psum(az));
            const float n = tanhf_(inn + r * (psum(an) + bhn));
            const float hnew = fmaf(z, hprev - n, n);  // (1-z)*n + z*h
            ring[t & 15][chain][j] = hnew;
            hprev = hnew;
            asm volatile("bar.sync %0, 64;" :: "r"(barid) : "memory");
        };

#pragma unroll 1
        for (int blk = 0; blk < TT / 4; ++blk) {
            const int t0 = blk * 4;
            if ((blk & 1) == 0 && blk) {
                // entering t0=8m: prefetch will reach gi step 8m+11 (block m+1)
                const unsigned need = (unsigned)min((blk >> 1) + 2, NBLK);
                if (ld_acquire_u32(&flags[chain]) < need)
                    while (ld_acquire_u32(&flags[chain]) < need) __nanosleep(128);
            }
            const bool pf = (blk + 1 < TT / 4);
            const float* p = gib + (size_t)(t0 + 4) * GG;

            { const float ir = cr0, iz = cz0, inn = cn0;
              if (pf) { cr0 = ldg_plain(p + 0 * GG); cz0 = ldg_plain(p + 0 * GG + 64); cn0 = ldg_plain(p + 0 * GG + 128); }
              step(t0 + 0, ir, iz, inn); }
            { const float ir = cr1, iz = cz1, inn = cn1;
              if (pf) { cr1 = ldg_plain(p + 1 * GG); cz1 = ldg_plain(p + 1 * GG + 64); cn1 = ldg_plain(p + 1 * GG + 128); }
              step(t0 + 1, ir, iz, inn); }
            { const float ir = cr2, iz = cz2, inn = cn2;
              if (pf) { cr2 = ldg_plain(p + 2 * GG); cz2 = ldg_plain(p + 2 * GG + 64); cn2 = ldg_plain(p + 2 * GG + 128); }
              step(t0 + 2, ir, iz, inn); }
            { const float ir = cr3, iz = cz3, inn = cn3;
              if (pf) { cr3 = ldg_plain(p + 3 * GG); cz3 = ldg_plain(p + 3 * GG + 64); cn3 = ldg_plain(p + 3 * GG + 128); }
              step(t0 + 3, ir, iz, inn); }

            if (blk & 1) {
                // flush steps tb..tb+7 (ring slots (tb&15)..+7), coalesced.
                // Safe: these slots are next overwritten >= 9 barriers later.
                const int tb = t0 - 4;               // multiple of 8
                const int sb = tb & 15;              // 0 or 8
#pragma unroll
                for (int q = 0; q < 2; ++q) {
                    const int idx  = q * 64 + j;     // 0..127
                    const int toff = idx >> 4;       // 0..7
                    const int jq   = idx & 15;       // float4 index within row
                    const float4 v = ((const float4*)ring[sb + toff][chain])[jq];
                    ((float4*)(hbase + (size_t)(tb + toff) * HID))[jq] = v;
                }
            }
        }
    }
}

// ================== K3: out proj + LN =======================================
// 256 threads / 8 warps; w2 packed in smem [k2][64] (conflict-free LDS.64);
// each warp processes EIGHT rows per iteration (was 4): the per-k2 weight
// LDS pair is amortized over 8 fma2 rows instead of 4, improving the
// fma2:LDS issue ratio from 256:192 to 512:256 per iteration (R12/R13 data
// showed this kernel is LDS+issue bound at 43%, NOT occupancy bound).
__global__ void __launch_bounds__(256) k_outproj(const float* __restrict__ w2,
                                                 const float* __restrict__ b2,
                                                 const float* __restrict__ g2,
                                                 const float* __restrict__ bb2,
                                                 float* __restrict__ out)
{
    const int tid  = threadIdx.x;
    const int wid  = tid >> 5;
    const int lane = tid & 31;
    const int j0 = lane, j1 = lane + 32;

    __shared__ __align__(16) u64   w2p[32][64];     // 16 KB
    __shared__ __align__(16) float hst[8][8][64];   // 16 KB, per-warp staging

    for (int idx = tid; idx < 32 * 64; idx += 256) {
        const int k2 = idx >> 6, jj = idx & 63;
        w2p[k2][jj] = pack2(w2[(size_t)(2 * k2) * DPK + jj],
                            w2[(size_t)(2 * k2 + 1) * DPK + jj]);
    }
    __syncthreads();

    const float bo0 = b2[j0], bo1 = b2[j1];
    const float lg0 = g2[j0], lg1 = g2[j1];
    const float lb0 = bb2[j0], lb1 = bb2[j1];

    const size_t stride = (size_t)gridDim.x * 64;
    for (size_t base = (size_t)blockIdx.x * 64 + wid * 8; base < (size_t)NROWS;
         base += stride) {
        // 8 rows in flight (front-batched LDG.64s)
#pragma unroll
        for (int rr = 0; rr < 8; ++rr) {
            const float2 h = ((const float2*)(g_hseq + (base + rr) * HID))[lane];
            ((float2*)hst[wid][rr])[lane] = h;
        }
        __syncwarp();

        u64 acc0[8], acc1[8];
#pragma unroll
        for (int rr = 0; rr < 8; ++rr) { acc0[rr] = 0; acc1[rr] = 0; }
#pragma unroll
        for (int k2 = 0; k2 < 32; ++k2) {
            const u64 w0 = w2p[k2][j0];
            const u64 w1v = w2p[k2][j1];
#pragma unroll
            for (int rr = 0; rr < 8; ++rr) {
                const u64 pH = ((const u64*)hst[wid][rr])[k2];  // broadcast
                acc0[rr] = fma2(w0,  pH, acc0[rr]);
                acc1[rr] = fma2(w1v, pH, acc1[rr]);
            }
        }

#pragma unroll
        for (int rr = 0; rr < 8; ++rr) {
            float o0 = psum(acc0[rr]) + bo0;
            float o1 = psum(acc1[rr]) + bo1;
            float s = o0 + o1;
#pragma unroll
            for (int o = 16; o; o >>= 1) s += __shfl_xor_sync(0xffffffffu, s, o);
            const float m = s * (1.f / 64.f);
            const float d0 = o0 - m, d1 = o1 - m;
            float q = d0 * d0 + d1 * d1;
#pragma unroll
            for (int o = 16; o; o >>= 1) q += __shfl_xor_sync(0xffffffffu, q, o);
            const float rs = rsqrtf(q * (1.f / 64.f) + EPS);
            const size_t row = base + rr;
            out[row * DPK + j0] = d0 * rs * lg0 + lb0;
            out[row * DPK + j1] = d1 * rs * lg1 + lb1;
        }
        __syncwarp();   // hst slot reused next iteration
    }
}

// ================== launcher =================================================
extern "C" void kernel_launch(void* const* d_in, const int* in_sizes, int n_in,
                              void* d_out, int out_size)
{
    const float* drug = (const float*)d_in[0];
    const float* w1   = (const float*)d_in[1];
    const float* b1   = (const float*)d_in[2];
    const float* ln1g = (const float*)d_in[3];
    const float* ln1b = (const float*)d_in[4];
    const float* Wih  = (const float*)d_in[5];
    const float* bih  = (const float*)d_in[6];
    const float* Whh  = (const float*)d_in[7];
    const float* bhh  = (const float*)d_in[8];
    const float* w2   = (const float*)d_in[9];
    const float* b2   = (const float*)d_in[10];
    const float* ln2g = (const float*)d_in[11];
    const float* ln2b = (const float*)d_in[12];
    float* out = (float*)d_out;

    k_inproj<<<NROWS / 8, 256>>>(drug, w1, b1, ln1g, ln1b);
    k_gru<<<BB / CH, 256>>>(Wih, bih, Whh, bhh);
    k_outproj<<<1024, 256>>>(w2, b2, ln2g, ln2b, out);
}

// round 15
// speedup vs baseline: 1.2731x; 1.0044x over previous
#include <cuda_runtime.h>
#include <cuda_bf16.h>
#include <cstdint>

// Problem constants
#define BB   256
#define TT   2048
#define IND  6
#define HID  64
#define GG   192          // 3*HID
#define DPK  64
#define NROWS (BB*TT)     // 524288
#define EPS  1e-5f
#define CH   2            // chains per GRU CTA
#define NBLK (TT/8)       // 256 gi blocks of 8 timesteps

typedef unsigned long long u64;

// ---------------- scratch (allocation-free: __device__ globals) -------------
__device__ float g_x[(size_t)NROWS * HID];       // 128 MB : post input-proj activations
// gi J-MAJOR: index = row*GG + gate*64 + j; produced INSIDE k_gru by gi warps.
// biases pre-folded: r,z gates carry b_ih+b_hh; n gate carries b_ih only.
__device__ float g_gi[(size_t)NROWS * GG];       // 402 MB
__device__ float g_hseq[(size_t)NROWS * HID];    // 128 MB : GRU hidden states [b][t][j]

// ---------------- packed f32x2 helpers --------------------------------------
__device__ __forceinline__ u64 fma2(u64 a, u64 b, u64 c) {
    u64 d;
    asm("fma.rn.f32x2 %0, %1, %2, %3;" : "=l"(d) : "l"(a), "l"(b), "l"(c));
    return d;
}
__device__ __forceinline__ u64 add2(u64 a, u64 b) {
    u64 d;
    asm("add.rn.f32x2 %0, %1, %2;" : "=l"(d) : "l"(a), "l"(b));
    return d;
}
__device__ __forceinline__ u64 pack2(float a, float b) {
    u64 r;
    asm("mov.b64 %0, {%1,%2};" : "=l"(r) : "f"(a), "f"(b));
    return r;
}
__device__ __forceinline__ float psum(u64 a) {
    return __uint_as_float((unsigned)(a & 0xffffffffull)) +
           __uint_as_float((unsigned)(a >> 32));
}
// plain (coherent) global load — rec must NOT use __ldg for gi: the RO/NC path
// may serve stale data for values written during this kernel by gi warps.
__device__ __forceinline__ float ldg_plain(const float* p) {
    float v;
    asm volatile("ld.global.f32 %0, [%1];" : "=f"(v) : "l"(p));
    return v;
}
__device__ __forceinline__ unsigned ld_acquire_u32(const unsigned* p) {
    unsigned v;
    asm volatile("ld.acquire.cta.u32 %0, [%1];" : "=r"(v) : "l"(p) : "memory");
    return v;
}
__device__ __forceinline__ void st_release_u32(unsigned* p, unsigned v) {
    asm volatile("st.release.cta.u32 [%0], %1;" :: "l"(p), "r"(v) : "memory");
}
// cp.async 8-byte (LDGSTS.E.64): dst is a 32-bit shared address
__device__ __forceinline__ uint32_t smem_u32(const void* p) {
    uint32_t a;
    asm("{ .reg .u64 t; cvta.to.shared.u64 t, %1; cvt.u32.u64 %0, t; }"
        : "=r"(a) : "l"(p));
    return a;
}
__device__ __forceinline__ void cp_async8(uint32_t dst, const void* src) {
    asm volatile("cp.async.ca.shared.global [%0], [%1], 8;" :: "r"(dst), "l"(src));
}
#define CP_COMMIT() asm volatile("cp.async.commit_group;" ::: "memory")
#define CP_WAIT1()  asm volatile("cp.async.wait_group 1;"  ::: "memory")
#define CP_WAIT0()  asm volatile("cp.async.wait_group 0;"  ::: "memory")

// EXACT-path activations (validated rel_err ~2.5e-7 over the full recurrence).
// tanh.approx is banned anywhere upstream of the recurrence (R5: per-step
// errors compound to ~0.15).
__device__ __forceinline__ float sigmoidf_(float x) {
    return __fdividef(1.f, 1.f + __expf(-x));
}
__device__ __forceinline__ float tanhf_(float x) {
    float e = __expf(2.f * x);
    return 1.f - __fdividef(2.f, e + 1.f);   // safe at e->inf (->1) and e->0 (->-1)
}

// GELU with Abramowitz-Stegun 7.1.26 erf (|eps| <= 1.5e-7 ABSOLUTE -- at the
// level of fp32 noise already carried; NOT a 5e-4-class approx like R5's
// tanh.approx). ~14 ops vs libdevice erff's ~30.
__device__ __forceinline__ float gelu_erf(float y) {
    const float kk = 0.70710678118654752f;     // 1/sqrt(2)
    const float x  = fabsf(y) * kk;
    const float t  = __fdividef(1.f, fmaf(0.3275911f, x, 1.f));
    float p = fmaf(1.061405429f, t, -1.453152027f);
    p = fmaf(p, t,  1.421413741f);
    p = fmaf(p, t, -0.284496736f);
    p = fmaf(p, t,  0.254829592f);
    p = p * t;
    const float e    = __expf(-x * x);
    const float erfa = fmaf(-p, e, 1.f);
    const float erfv = copysignf(erfa, y);
    return 0.5f * y * (1.f + erfv);
}

// ================== K1a: input proj + LN + GELU =============================
// one warp per (b,t) row; each lane owns output cols lane, lane+32.
__global__ void k_inproj(const float* __restrict__ ce,
                         const float* __restrict__ w1,
                         const float* __restrict__ b1,
                         const float* __restrict__ g1,
                         const float* __restrict__ bb1)
{
    const int wid  = threadIdx.x >> 5;
    const int lane = threadIdx.x & 31;
    const size_t row = (size_t)blockIdx.x * 8 + wid;   // grid = NROWS/8

    const float* c = ce + row * IND;
    float v0 = b1[lane], v1 = b1[lane + 32];
#pragma unroll
    for (int i = 0; i < IND; ++i) {
        float ci = __ldg(c + i);
        v0 = fmaf(ci, w1[i * HID + lane],      v0);
        v1 = fmaf(ci, w1[i * HID + lane + 32], v1);
    }
    float s = v0 + v1;
#pragma unroll
    for (int o = 16; o; o >>= 1) s += __shfl_xor_sync(0xffffffffu, s, o);
    const float m = s * (1.f / 64.f);
    const float d0 = v0 - m, d1 = v1 - m;
    float q = d0 * d0 + d1 * d1;
#pragma unroll
    for (int o = 16; o; o >>= 1) q += __shfl_xor_sync(0xffffffffu, q, o);
    const float rs = rsqrtf(q * (1.f / 64.f) + EPS);
    const float y0 = d0 * rs * g1[lane]      + bb1[lane];
    const float y1 = d1 * rs * g1[lane + 32] + bb1[lane + 32];
    g_x[row * HID + lane]      = gelu_erf(y0);
    g_x[row * HID + lane + 32] = gelu_erf(y1);
}

// ================== K2: FUSED gi-producer + GRU recurrence (R12) ============
// grid = 128 CTAs, block = 256 threads, 2 chains:
//   tid   0- 63 : gi producer, chain 0  (warps 0,1 -- LOW wid = low priority)
//   tid  64-127 : gi producer, chain 1  (warps 2,3)
//   tid 128-191 : recurrence,  chain 0  (warps 4,5 -- HIGH wid = priority)
//   tid 192-255 : recurrence,  chain 1  (warps 6,7)
// SMSP s hosts warp s (gi) + warp s+4 (rec): the gi warp has NO per-step
// barrier, so it streams fma2 into the rec warp's exposed-latency windows.
// Measured (R12/R14): gru ~705cyc/step = rec(410)+gi(330) issue-saturated.
__global__ void __launch_bounds__(256, 1) k_gru(const float* __restrict__ Wih,
                                                const float* __restrict__ bih,
                                                const float* __restrict__ Whh,
                                                const float* __restrict__ bhh)
{
    const int tid   = threadIdx.x;
    const int role  = tid >> 7;            // 0 = gi producer, 1 = recurrence
    const int chain = (tid >> 6) & 1;
    const int j     = tid & 63;
    const size_t brow = (size_t)blockIdx.x * CH + chain;

    __shared__ __align__(16) float ring[16][CH][64];  // 8 KB h history
    __shared__ __align__(16) float xsh[CH][8][64];    // 4 KB x staging (gi)
    __shared__ unsigned flags[CH];                    // gi blocks completed

    if (tid < CH) flags[tid] = 0;
    __syncthreads();                                  // flags visible to all

    if (role == 0) {
        // ================= gi producer =================
        const unsigned gibar = 3 + chain;             // 64-thread named barrier
        u64 wr[32], wz[32], wn[32];
        {
            const u64* rrow = (const u64*)(Wih + (size_t)j * HID);
            const u64* zrow = (const u64*)(Wih + (size_t)(64 + j) * HID);
            const u64* nrow = (const u64*)(Wih + (size_t)(128 + j) * HID);
#pragma unroll
            for (int k = 0; k < 32; ++k) { wr[k] = rrow[k]; wz[k] = zrow[k]; wn[k] = nrow[k]; }
        }
        const float bir = bih[j]       + bhh[j];
        const float biz = bih[64 + j]  + bhh[64 + j];
        const float bin = bih[128 + j];

        const float* xb   = g_x  + brow * (size_t)TT * HID;
        float*       gout = g_gi + brow * (size_t)TT * GG;

        float xr[8];
#pragma unroll
        for (int r = 0; r < 8; ++r) xr[r] = __ldg(xb + (size_t)r * HID + j);

#pragma unroll 1
        for (int b = 0; b < NBLK; ++b) {
            asm volatile("bar.sync %0, 64;" :: "r"(gibar) : "memory");
            if (j == 0 && b) st_release_u32(&flags[chain], (unsigned)b);
#pragma unroll
            for (int r = 0; r < 8; ++r) xsh[chain][r][j] = xr[r];
            asm volatile("bar.sync %0, 64;" :: "r"(gibar) : "memory");
            if (b + 1 < NBLK) {
                const float* xn = xb + (size_t)(b + 1) * 8 * HID + j;
#pragma unroll
                for (int r = 0; r < 8; ++r) xr[r] = __ldg(xn + (size_t)r * HID);
            }
#pragma unroll
            for (int r = 0; r < 8; ++r) {
                const ulonglong2* xv = (const ulonglong2*)xsh[chain][r];
                u64 ar0 = 0, ar1 = 0, az0 = 0, az1 = 0, an0 = 0, an1 = 0;
#pragma unroll
                for (int kk = 0; kk < 16; ++kk) {
                    const ulonglong2 p = xv[kk];        // LDS.128 broadcast
                    ar0 = fma2(wr[2 * kk],     p.x, ar0);
                    az0 = fma2(wz[2 * kk],     p.x, az0);
                    an0 = fma2(wn[2 * kk],     p.x, an0);
                    ar1 = fma2(wr[2 * kk + 1], p.y, ar1);
                    az1 = fma2(wz[2 * kk + 1], p.y, az1);
                    an1 = fma2(wn[2 * kk + 1], p.y, an1);
                }
                float* d = gout + (size_t)(b * 8 + r) * GG + j;
                d[0]   = psum(add2(ar0, ar1)) + bir;
                d[64]  = psum(add2(az0, az1)) + biz;
                d[128] = psum(add2(an0, an1)) + bin;
            }
        }
        asm volatile("bar.sync %0, 64;" :: "r"(gibar) : "memory");
        if (j == 0) st_release_u32(&flags[chain], (unsigned)NBLK);

    } else {
        // ================= recurrence (R8 inner loop) =================
        const unsigned barid = 1 + chain;             // 64-thread named barrier
        u64 wr[32], wz[32], wn[32];
        {
            const u64* rrow = (const u64*)(Whh + (size_t)j * HID);
            const u64* zrow = (const u64*)(Whh + (size_t)(64 + j) * HID);
            const u64* nrow = (const u64*)(Whh + (size_t)(128 + j) * HID);
#pragma unroll
            for (int k = 0; k < 32; ++k) { wr[k] = rrow[k]; wz[k] = zrow[k]; wn[k] = nrow[k]; }
        }
        const float bhn = bhh[128 + j];

        ring[15][chain][j] = 0.f;                     // h_{-1} = 0
        float hprev = 0.f;

        const float* gib = g_gi + brow * (size_t)TT * GG + j;
        float* hbase = g_hseq + brow * (size_t)TT * HID;

        // wait for gi blocks 0,1 then prime the 4-step gi buffer
        while (ld_acquire_u32(&flags[chain]) < 2u) __nanosleep(128);
        float cr0 = ldg_plain(gib + 0 * GG), cz0 = ldg_plain(gib + 0 * GG + 64), cn0 = ldg_plain(gib + 0 * GG + 128);
        float cr1 = ldg_plain(gib + 1 * GG), cz1 = ldg_plain(gib + 1 * GG + 64), cn1 = ldg_plain(gib + 1 * GG + 128);
        float cr2 = ldg_plain(gib + 2 * GG), cz2 = ldg_plain(gib + 2 * GG + 64), cn2 = ldg_plain(gib + 2 * GG + 128);
        float cr3 = ldg_plain(gib + 3 * GG), cz3 = ldg_plain(gib + 3 * GG + 64), cn3 = ldg_plain(gib + 3 * GG + 128);

        asm volatile("bar.sync %0, 64;" :: "r"(barid) : "memory");

        auto step = [&](const int t, const float ir, const float iz, const float inn) {
            const ulonglong2* hv = (const ulonglong2*)ring[(t + 15) & 15][chain];
            u64 ar = 0, az = 0, an = 0;
#pragma unroll
            for (int kk = 0; kk < 16; ++kk) {          // full 64-wide dot
                const ulonglong2 p = hv[kk];           // LDS.128 broadcast
                ar = fma2(wr[2 * kk],     p.x, ar);
                az = fma2(wz[2 * kk],     p.x, az);
                an = fma2(wn[2 * kk],     p.x, an);
                ar = fma2(wr[2 * kk + 1], p.y, ar);
                az = fma2(wz[2 * kk + 1], p.y, az);
                an = fma2(wn[2 * kk + 1], p.y, an);
            }
            const float r = sigmoidf_(ir + psum(ar));  // biases pre-folded in gi
            const float z = sigmoidf_(iz + psum(az));
            const float n = tanhf_(inn + r * (psum(an) + bhn));
            const float hnew = fmaf(z, hprev - n, n);  // (1-z)*n + z*h
            ring[t & 15][chain][j] = hnew;
            hprev = hnew;
            asm volatile("bar.sync %0, 64;" :: "r"(barid) : "memory");
        };

#pragma unroll 1
        for (int blk = 0; blk < TT / 4; ++blk) {
            const int t0 = blk * 4;
            if ((blk & 1) == 0 && blk) {
                // entering t0=8m: prefetch will reach gi step 8m+11 (block m+1)
                const unsigned need = (unsigned)min((blk >> 1) + 2, NBLK);
                if (ld_acquire_u32(&flags[chain]) < need)
                    while (ld_acquire_u32(&flags[chain]) < need) __nanosleep(128);
            }
            const bool pf = (blk + 1 < TT / 4);
            const float* p = gib + (size_t)(t0 + 4) * GG;

            { const float ir = cr0, iz = cz0, inn = cn0;
              if (pf) { cr0 = ldg_plain(p + 0 * GG); cz0 = ldg_plain(p + 0 * GG + 64); cn0 = ldg_plain(p + 0 * GG + 128); }
              step(t0 + 0, ir, iz, inn); }
            { const float ir = cr1, iz = cz1, inn = cn1;
              if (pf) { cr1 = ldg_plain(p + 1 * GG); cz1 = ldg_plain(p + 1 * GG + 64); cn1 = ldg_plain(p + 1 * GG + 128); }
              step(t0 + 1, ir, iz, inn); }
            { const float ir = cr2, iz = cz2, inn = cn2;
              if (pf) { cr2 = ldg_plain(p + 2 * GG); cz2 = ldg_plain(p + 2 * GG + 64); cn2 = ldg_plain(p + 2 * GG + 128); }
              step(t0 + 2, ir, iz, inn); }
            { const float ir = cr3, iz = cz3, inn = cn3;
              if (pf) { cr3 = ldg_plain(p + 3 * GG); cz3 = ldg_plain(p + 3 * GG + 64); cn3 = ldg_plain(p + 3 * GG + 128); }
              step(t0 + 3, ir, iz, inn); }

            if (blk & 1) {
                // flush steps tb..tb+7 (ring slots (tb&15)..+7), coalesced.
                // Safe: these slots are next overwritten >= 9 barriers later.
                const int tb = t0 - 4;               // multiple of 8
                const int sb = tb & 15;              // 0 or 8
#pragma unroll
                for (int q = 0; q < 2; ++q) {
                    const int idx  = q * 64 + j;     // 0..127
                    const int toff = idx >> 4;       // 0..7
                    const int jq   = idx & 15;       // float4 index within row
                    const float4 v = ((const float4*)ring[sb + toff][chain])[jq];
                    ((float4*)(hbase + (size_t)(tb + toff) * HID))[jq] = v;
                }
            }
        }
    }
}

// ================== K3: out proj + LN =======================================
// 256 threads / 8 warps; w2 packed in smem [k2][64] (conflict-free LDS.64);
// each warp processes EIGHT rows per iteration with a cp.async (LDGSTS)
// DOUBLE-BUFFERED smem pipeline: next iteration's rows stream in while the
// fma loop chews the current buffer (R14 data: 43.7% issue -> iteration-head
// LDG latency was exposed; cp.async hides it with zero register cost).
__global__ void __launch_bounds__(256) k_outproj(const float* __restrict__ w2,
                                                 const float* __restrict__ b2,
                                                 const float* __restrict__ g2,
                                                 const float* __restrict__ bb2,
                                                 float* __restrict__ out)
{
    const int tid  = threadIdx.x;
    const int wid  = tid >> 5;
    const int lane = tid & 31;
    const int j0 = lane, j1 = lane + 32;

    __shared__ __align__(16) u64   w2p[32][64];        // 16 KB
    __shared__ __align__(16) float hst[2][8][8][64];   // 32 KB double buffer

    for (int idx = tid; idx < 32 * 64; idx += 256) {
        const int k2 = idx >> 6, jj = idx & 63;
        w2p[k2][jj] = pack2(w2[(size_t)(2 * k2) * DPK + jj],
                            w2[(size_t)(2 * k2 + 1) * DPK + jj]);
    }
    __syncthreads();

    const float bo0 = b2[j0], bo1 = b2[j1];
    const float lg0 = g2[j0], lg1 = g2[j1];
    const float lb0 = bb2[j0], lb1 = bb2[j1];

    const size_t stride = (size_t)gridDim.x * 64;
    const size_t base0  = (size_t)blockIdx.x * 64 + wid * 8;

    auto issue8 = [&](size_t base, int buf) {
#pragma unroll
        for (int rr = 0; rr < 8; ++rr)
            cp_async8(smem_u32(&hst[buf][wid][rr][lane * 2]),
                      g_hseq + (base + rr) * HID + lane * 2);
        CP_COMMIT();
    };

    if (base0 < (size_t)NROWS) issue8(base0, 0);   // prime buffer 0

    int buf = 0;
    for (size_t base = base0; base < (size_t)NROWS; base += stride, buf ^= 1) {
        const size_t nb = base + stride;
        if (nb < (size_t)NROWS) { issue8(nb, buf ^ 1); CP_WAIT1(); }
        else                    { CP_WAIT0(); }
        __syncwarp();

        u64 acc0[8], acc1[8];
#pragma unroll
        for (int rr = 0; rr < 8; ++rr) { acc0[rr] = 0; acc1[rr] = 0; }
#pragma unroll
        for (int k2 = 0; k2 < 32; ++k2) {
            const u64 w0  = w2p[k2][j0];
            const u64 w1v = w2p[k2][j1];
#pragma unroll
            for (int rr = 0; rr < 8; ++rr) {
                const u64 pH = ((const u64*)hst[buf][wid][rr])[k2];  // broadcast
                acc0[rr] = fma2(w0,  pH, acc0[rr]);
                acc1[rr] = fma2(w1v, pH, acc1[rr]);
            }
        }

#pragma unroll
        for (int rr = 0; rr < 8; ++rr) {
            float o0 = psum(acc0[rr]) + bo0;
            float o1 = psum(acc1[rr]) + bo1;
            float s = o0 + o1;
#pragma unroll
            for (int o = 16; o; o >>= 1) s += __shfl_xor_sync(0xffffffffu, s, o);
            const float m = s * (1.f / 64.f);
            const float d0 = o0 - m, d1 = o1 - m;
            float q = d0 * d0 + d1 * d1;
#pragma unroll
            for (int o = 16; o; o >>= 1) q += __shfl_xor_sync(0xffffffffu, q, o);
            const float rs = rsqrtf(q * (1.f / 64.f) + EPS);
            const size_t row = base + rr;
            out[row * DPK + j0] = d0 * rs * lg0 + lb0;
            out[row * DPK + j1] = d1 * rs * lg1 + lb1;
        }
        __syncwarp();   // all lanes done reading hst[buf] before it is refilled
    }
}

// ================== launcher =================================================
extern "C" void kernel_launch(void* const* d_in, const int* in_sizes, int n_in,
                              void* d_out, int out_size)
{
    const float* drug = (const float*)d_in[0];
    const float* w1   = (const float*)d_in[1];
    const float* b1   = (const float*)d_in[2];
    const float* ln1g = (const float*)d_in[3];
    const float* ln1b = (const float*)d_in[4];
    const float* Wih  = (const float*)d_in[5];
    const float* bih  = (const float*)d_in[6];
    const float* Whh  = (const float*)d_in[7];
    const float* bhh  = (const float*)d_in[8];
    const float* w2   = (const float*)d_in[9];
    const float* b2   = (const float*)d_in[10];
    const float* ln2g = (const float*)d_in[11];
    const float* ln2b = (const float*)d_in[12];
    float* out = (float*)d_out;

    k_inproj<<<NROWS / 8, 256>>>(drug, w1, b1, ln1g, ln1b);
    k_gru<<<BB / CH, 256>>>(Wih, bih, Whh, bhh);
    k_outproj<<<1024, 256>>>(w2, b2, ln2g, ln2b, out);
}

// round 16
// speedup vs baseline: 1.2816x; 1.0066x over previous
#include <cuda_runtime.h>
#include <cuda_bf16.h>
#include <cstdint>

// Problem constants
#define BB   256
#define TT   2048
#define IND  6
#define HID  64
#define GG   192          // 3*HID
#define DPK  64
#define NROWS (BB*TT)     // 524288
#define EPS  1e-5f
#define CH   2            // chains per GRU CTA
#define NBLK (TT/8)       // 256 gi blocks of 8 timesteps

typedef unsigned long long u64;

// ---------------- scratch (allocation-free: __device__ globals) -------------
__device__ float g_x[(size_t)NROWS * HID];       // 128 MB : post input-proj activations
// gi J-MAJOR: index = row*GG + gate*64 + j; produced INSIDE k_gru by gi warps.
// biases pre-folded: r,z gates carry b_ih+b_hh; n gate carries b_ih only.
__device__ float g_gi[(size_t)NROWS * GG];       // 402 MB
__device__ float g_hseq[(size_t)NROWS * HID];    // 128 MB : GRU hidden states [b][t][j]

// ---------------- packed f32x2 helpers --------------------------------------
__device__ __forceinline__ u64 fma2(u64 a, u64 b, u64 c) {
    u64 d;
    asm("fma.rn.f32x2 %0, %1, %2, %3;" : "=l"(d) : "l"(a), "l"(b), "l"(c));
    return d;
}
__device__ __forceinline__ u64 add2(u64 a, u64 b) {
    u64 d;
    asm("add.rn.f32x2 %0, %1, %2;" : "=l"(d) : "l"(a), "l"(b));
    return d;
}
__device__ __forceinline__ u64 pack2(float a, float b) {
    u64 r;
    asm("mov.b64 %0, {%1,%2};" : "=l"(r) : "f"(a), "f"(b));
    return r;
}
__device__ __forceinline__ float psum(u64 a) {
    return __uint_as_float((unsigned)(a & 0xffffffffull)) +
           __uint_as_float((unsigned)(a >> 32));
}
// plain (coherent) global load — rec must NOT use __ldg for gi: the RO/NC path
// may serve stale data for values written during this kernel by gi warps.
__device__ __forceinline__ float ldg_plain(const float* p) {
    float v;
    asm volatile("ld.global.f32 %0, [%1];" : "=f"(v) : "l"(p));
    return v;
}
__device__ __forceinline__ unsigned ld_acquire_u32(const unsigned* p) {
    unsigned v;
    asm volatile("ld.acquire.cta.u32 %0, [%1];" : "=r"(v) : "l"(p) : "memory");
    return v;
}
__device__ __forceinline__ void st_release_u32(unsigned* p, unsigned v) {
    asm volatile("st.release.cta.u32 [%0], %1;" :: "l"(p), "r"(v) : "memory");
}
// cp.async 8-byte (LDGSTS.E.64): dst is a 32-bit shared address
__device__ __forceinline__ uint32_t smem_u32(const void* p) {
    uint32_t a;
    asm("{ .reg .u64 t; cvta.to.shared.u64 t, %1; cvt.u32.u64 %0, t; }"
        : "=r"(a) : "l"(p));
    return a;
}
__device__ __forceinline__ void cp_async8(uint32_t dst, const void* src) {
    asm volatile("cp.async.ca.shared.global [%0], [%1], 8;" :: "r"(dst), "l"(src));
}
#define CP_COMMIT() asm volatile("cp.async.commit_group;" ::: "memory")
#define CP_WAIT1()  asm volatile("cp.async.wait_group 1;"  ::: "memory")
#define CP_WAIT0()  asm volatile("cp.async.wait_group 0;"  ::: "memory")

// EXACT-path activations (validated rel_err ~2.5e-7 over the full recurrence).
// tanh.approx is banned anywhere upstream of the recurrence (R5: per-step
// errors compound to ~0.15).
__device__ __forceinline__ float sigmoidf_(float x) {
    return __fdividef(1.f, 1.f + __expf(-x));
}
__device__ __forceinline__ float tanhf_(float x) {
    float e = __expf(2.f * x);
    return 1.f - __fdividef(2.f, e + 1.f);   // safe at e->inf (->1) and e->0 (->-1)
}

// GELU with Abramowitz-Stegun 7.1.26 erf (|eps| <= 1.5e-7 ABSOLUTE -- fp32
// noise level; validated R15 at rel_err 2.58e-7). ~14 ops vs erff's ~30.
__device__ __forceinline__ float gelu_erf(float y) {
    const float kk = 0.70710678118654752f;     // 1/sqrt(2)
    const float x  = fabsf(y) * kk;
    const float t  = __fdividef(1.f, fmaf(0.3275911f, x, 1.f));
    float p = fmaf(1.061405429f, t, -1.453152027f);
    p = fmaf(p, t,  1.421413741f);
    p = fmaf(p, t, -0.284496736f);
    p = fmaf(p, t,  0.254829592f);
    p = p * t;
    const float e    = __expf(-x * x);
    const float erfa = fmaf(-p, e, 1.f);
    const float erfv = copysignf(erfa, y);
    return 0.5f * y * (1.f + erfv);
}

// ================== K1a: input proj + LN + GELU =============================
// one warp per (b,t) row; each lane owns output cols lane, lane+32.
__global__ void k_inproj(const float* __restrict__ ce,
                         const float* __restrict__ w1,
                         const float* __restrict__ b1,
                         const float* __restrict__ g1,
                         const float* __restrict__ bb1)
{
    const int wid  = threadIdx.x >> 5;
    const int lane = threadIdx.x & 31;
    const size_t row = (size_t)blockIdx.x * 8 + wid;   // grid = NROWS/8

    const float* c = ce + row * IND;
    float v0 = b1[lane], v1 = b1[lane + 32];
#pragma unroll
    for (int i = 0; i < IND; ++i) {
        float ci = __ldg(c + i);
        v0 = fmaf(ci, w1[i * HID + lane],      v0);
        v1 = fmaf(ci, w1[i * HID + lane + 32], v1);
    }
    float s = v0 + v1;
#pragma unroll
    for (int o = 16; o; o >>= 1) s += __shfl_xor_sync(0xffffffffu, s, o);
    const float m = s * (1.f / 64.f);
    const float d0 = v0 - m, d1 = v1 - m;
    float q = d0 * d0 + d1 * d1;
#pragma unroll
    for (int o = 16; o; o >>= 1) q += __shfl_xor_sync(0xffffffffu, q, o);
    const float rs = rsqrtf(q * (1.f / 64.f) + EPS);
    const float y0 = d0 * rs * g1[lane]      + bb1[lane];
    const float y1 = d1 * rs * g1[lane + 32] + bb1[lane + 32];
    g_x[row * HID + lane]      = gelu_erf(y0);
    g_x[row * HID + lane + 32] = gelu_erf(y1);
}

// ================== K2: FUSED gi-producer + GRU recurrence (R12) ============
// grid = 128 CTAs, block = 256 threads, 2 chains:
//   tid   0- 63 : gi producer, chain 0  (warps 0,1 -- LOW wid = low priority)
//   tid  64-127 : gi producer, chain 1  (warps 2,3)
//   tid 128-191 : recurrence,  chain 0  (warps 4,5 -- HIGH wid = priority)
//   tid 192-255 : recurrence,  chain 1  (warps 6,7)
// SMSP s hosts warp s (gi) + warp s+4 (rec): the gi warp has NO per-step
// barrier, so it streams fma2 into the rec warp's exposed-latency windows.
// Measured (R12/R14/R15): gru ~705cyc/step = rec(410)+gi(330), saturated.
// UNTOUCHED since R12 -- every modification attempt (R13 inproj fusion, R9-R11
// restructures) regressed.
__global__ void __launch_bounds__(256, 1) k_gru(const float* __restrict__ Wih,
                                                const float* __restrict__ bih,
                                                const float* __restrict__ Whh,
                                                const float* __restrict__ bhh)
{
    const int tid   = threadIdx.x;
    const int role  = tid >> 7;            // 0 = gi producer, 1 = recurrence
    const int chain = (tid >> 6) & 1;
    const int j     = tid & 63;
    const size_t brow = (size_t)blockIdx.x * CH + chain;

    __shared__ __align__(16) float ring[16][CH][64];  // 8 KB h history
    __shared__ __align__(16) float xsh[CH][8][64];    // 4 KB x staging (gi)
    __shared__ unsigned flags[CH];                    // gi blocks completed

    if (tid < CH) flags[tid] = 0;
    __syncthreads();                                  // flags visible to all

    if (role == 0) {
        // ================= gi producer =================
        const unsigned gibar = 3 + chain;             // 64-thread named barrier
        u64 wr[32], wz[32], wn[32];
        {
            const u64* rrow = (const u64*)(Wih + (size_t)j * HID);
            const u64* zrow = (const u64*)(Wih + (size_t)(64 + j) * HID);
            const u64* nrow = (const u64*)(Wih + (size_t)(128 + j) * HID);
#pragma unroll
            for (int k = 0; k < 32; ++k) { wr[k] = rrow[k]; wz[k] = zrow[k]; wn[k] = nrow[k]; }
        }
        const float bir = bih[j]       + bhh[j];
        const float biz = bih[64 + j]  + bhh[64 + j];
        const float bin = bih[128 + j];

        const float* xb   = g_x  + brow * (size_t)TT * HID;
        float*       gout = g_gi + brow * (size_t)TT * GG;

        float xr[8];
#pragma unroll
        for (int r = 0; r < 8; ++r) xr[r] = __ldg(xb + (size_t)r * HID + j);

#pragma unroll 1
        for (int b = 0; b < NBLK; ++b) {
            asm volatile("bar.sync %0, 64;" :: "r"(gibar) : "memory");
            if (j == 0 && b) st_release_u32(&flags[chain], (unsigned)b);
#pragma unroll
            for (int r = 0; r < 8; ++r) xsh[chain][r][j] = xr[r];
            asm volatile("bar.sync %0, 64;" :: "r"(gibar) : "memory");
            if (b + 1 < NBLK) {
                const float* xn = xb + (size_t)(b + 1) * 8 * HID + j;
#pragma unroll
                for (int r = 0; r < 8; ++r) xr[r] = __ldg(xn + (size_t)r * HID);
            }
#pragma unroll
            for (int r = 0; r < 8; ++r) {
                const ulonglong2* xv = (const ulonglong2*)xsh[chain][r];
                u64 ar0 = 0, ar1 = 0, az0 = 0, az1 = 0, an0 = 0, an1 = 0;
#pragma unroll
                for (int kk = 0; kk < 16; ++kk) {
                    const ulonglong2 p = xv[kk];        // LDS.128 broadcast
                    ar0 = fma2(wr[2 * kk],     p.x, ar0);
                    az0 = fma2(wz[2 * kk],     p.x, az0);
                    an0 = fma2(wn[2 * kk],     p.x, an0);
                    ar1 = fma2(wr[2 * kk + 1], p.y, ar1);
                    az1 = fma2(wz[2 * kk + 1], p.y, az1);
                    an1 = fma2(wn[2 * kk + 1], p.y, an1);
                }
                float* d = gout + (size_t)(b * 8 + r) * GG + j;
                d[0]   = psum(add2(ar0, ar1)) + bir;
                d[64]  = psum(add2(az0, az1)) + biz;
                d[128] = psum(add2(an0, an1)) + bin;
            }
        }
        asm volatile("bar.sync %0, 64;" :: "r"(gibar) : "memory");
        if (j == 0) st_release_u32(&flags[chain], (unsigned)NBLK);

    } else {
        // ================= recurrence (R8 inner loop) =================
        const unsigned barid = 1 + chain;             // 64-thread named barrier
        u64 wr[32], wz[32], wn[32];
        {
            const u64* rrow = (const u64*)(Whh + (size_t)j * HID);
            const u64* zrow = (const u64*)(Whh + (size_t)(64 + j) * HID);
            const u64* nrow = (const u64*)(Whh + (size_t)(128 + j) * HID);
#pragma unroll
            for (int k = 0; k < 32; ++k) { wr[k] = rrow[k]; wz[k] = zrow[k]; wn[k] = nrow[k]; }
        }
        const float bhn = bhh[128 + j];

        ring[15][chain][j] = 0.f;                     // h_{-1} = 0
        float hprev = 0.f;

        const float* gib = g_gi + brow * (size_t)TT * GG + j;
        float* hbase = g_hseq + brow * (size_t)TT * HID;

        // wait for gi blocks 0,1 then prime the 4-step gi buffer
        while (ld_acquire_u32(&flags[chain]) < 2u) __nanosleep(128);
        float cr0 = ldg_plain(gib + 0 * GG), cz0 = ldg_plain(gib + 0 * GG + 64), cn0 = ldg_plain(gib + 0 * GG + 128);
        float cr1 = ldg_plain(gib + 1 * GG), cz1 = ldg_plain(gib + 1 * GG + 64), cn1 = ldg_plain(gib + 1 * GG + 128);
        float cr2 = ldg_plain(gib + 2 * GG), cz2 = ldg_plain(gib + 2 * GG + 64), cn2 = ldg_plain(gib + 2 * GG + 128);
        float cr3 = ldg_plain(gib + 3 * GG), cz3 = ldg_plain(gib + 3 * GG + 64), cn3 = ldg_plain(gib + 3 * GG + 128);

        asm volatile("bar.sync %0, 64;" :: "r"(barid) : "memory");

        auto step = [&](const int t, const float ir, const float iz, const float inn) {
            const ulonglong2* hv = (const ulonglong2*)ring[(t + 15) & 15][chain];
            u64 ar = 0, az = 0, an = 0;
#pragma unroll
            for (int kk = 0; kk < 16; ++kk) {          // full 64-wide dot
                const ulonglong2 p = hv[kk];           // LDS.128 broadcast
                ar = fma2(wr[2 * kk],     p.x, ar);
                az = fma2(wz[2 * kk],     p.x, az);
                an = fma2(wn[2 * kk],     p.x, an);
                ar = fma2(wr[2 * kk + 1], p.y, ar);
                az = fma2(wz[2 * kk + 1], p.y, az);
                an = fma2(wn[2 * kk + 1], p.y, an);
            }
            const float r = sigmoidf_(ir + psum(ar));  // biases pre-folded in gi
            const float z = sigmoidf_(iz + psum(az));
            const float n = tanhf_(inn + r * (psum(an) + bhn));
            const float hnew = fmaf(z, hprev - n, n);  // (1-z)*n + z*h
            ring[t & 15][chain][j] = hnew;
            hprev = hnew;
            asm volatile("bar.sync %0, 64;" :: "r"(barid) : "memory");
        };

#pragma unroll 1
        for (int blk = 0; blk < TT / 4; ++blk) {
            const int t0 = blk * 4;
            if ((blk & 1) == 0 && blk) {
                // entering t0=8m: prefetch will reach gi step 8m+11 (block m+1)
                const unsigned need = (unsigned)min((blk >> 1) + 2, NBLK);
                if (ld_acquire_u32(&flags[chain]) < need)
                    while (ld_acquire_u32(&flags[chain]) < need) __nanosleep(128);
            }
            const bool pf = (blk + 1 < TT / 4);
            const float* p = gib + (size_t)(t0 + 4) * GG;

            { const float ir = cr0, iz = cz0, inn = cn0;
              if (pf) { cr0 = ldg_plain(p + 0 * GG); cz0 = ldg_plain(p + 0 * GG + 64); cn0 = ldg_plain(p + 0 * GG + 128); }
              step(t0 + 0, ir, iz, inn); }
            { const float ir = cr1, iz = cz1, inn = cn1;
              if (pf) { cr1 = ldg_plain(p + 1 * GG); cz1 = ldg_plain(p + 1 * GG + 64); cn1 = ldg_plain(p + 1 * GG + 128); }
              step(t0 + 1, ir, iz, inn); }
            { const float ir = cr2, iz = cz2, inn = cn2;
              if (pf) { cr2 = ldg_plain(p + 2 * GG); cz2 = ldg_plain(p + 2 * GG + 64); cn2 = ldg_plain(p + 2 * GG + 128); }
              step(t0 + 2, ir, iz, inn); }
            { const float ir = cr3, iz = cz3, inn = cn3;
              if (pf) { cr3 = ldg_plain(p + 3 * GG); cz3 = ldg_plain(p + 3 * GG + 64); cn3 = ldg_plain(p + 3 * GG + 128); }
              step(t0 + 3, ir, iz, inn); }

            if (blk & 1) {
                // flush steps tb..tb+7 (ring slots (tb&15)..+7), coalesced.
                // Safe: these slots are next overwritten >= 9 barriers later.
                const int tb = t0 - 4;               // multiple of 8
                const int sb = tb & 15;              // 0 or 8
#pragma unroll
                for (int q = 0; q < 2; ++q) {
                    const int idx  = q * 64 + j;     // 0..127
                    const int toff = idx >> 4;       // 0..7
                    const int jq   = idx & 15;       // float4 index within row
                    const float4 v = ((const float4*)ring[sb + toff][chain])[jq];
                    ((float4*)(hbase + (size_t)(tb + toff) * HID))[jq] = v;
                }
            }
        }
    }
}

// ================== K3: out proj + LN =======================================
// 256 threads / 8 warps; w2 packed in smem [k2][64]; 8 rows per warp-iter
// with cp.async double-buffered staging. R16 changes (R15 ncu: 44% issue,
// cp.async didn't help -> binding constraint was the LN epilogue's 8 rows x
// 2 trees x 5 dependent shfls ~ 2100 serial cycles/iter, plus u64-granular
// h reads):
//  (1) LN shfl trees INTERLEAVED level-major across all 8 rows: one 5-level
//      pipeline of 8 independent shfls per level (~350 cyc vs ~2100).
//  (2) h read as LDS.128 (ulonglong2, 2 k2 per load): 320 -> 192 LDS/iter.
__global__ void __launch_bounds__(256) k_outproj(const float* __restrict__ w2,
                                                 const float* __restrict__ b2,
                                                 const float* __restrict__ g2,
                                                 const float* __restrict__ bb2,
                                                 float* __restrict__ out)
{
    const int tid  = threadIdx.x;
    const int wid  = tid >> 5;
    const int lane = tid & 31;
    const int j0 = lane, j1 = lane + 32;

    __shared__ __align__(16) u64   w2p[32][64];        // 16 KB
    __shared__ __align__(16) float hst[2][8][8][64];   // 32 KB double buffer

    for (int idx = tid; idx < 32 * 64; idx += 256) {
        const int k2 = idx >> 6, jj = idx & 63;
        w2p[k2][jj] = pack2(w2[(size_t)(2 * k2) * DPK + jj],
                            w2[(size_t)(2 * k2 + 1) * DPK + jj]);
    }
    __syncthreads();

    const float bo0 = b2[j0], bo1 = b2[j1];
    const float lg0 = g2[j0], lg1 = g2[j1];
    const float lb0 = bb2[j0], lb1 = bb2[j1];

    const size_t stride = (size_t)gridDim.x * 64;
    const size_t base0  = (size_t)blockIdx.x * 64 + wid * 8;

    auto issue8 = [&](size_t base, int buf) {
#pragma unroll
        for (int rr = 0; rr < 8; ++rr)
            cp_async8(smem_u32(&hst[buf][wid][rr][lane * 2]),
                      g_hseq + (base + rr) * HID + lane * 2);
        CP_COMMIT();
    };

    if (base0 < (size_t)NROWS) issue8(base0, 0);   // prime buffer 0

    int buf = 0;
    for (size_t base = base0; base < (size_t)NROWS; base += stride, buf ^= 1) {
        const size_t nb = base + stride;
        if (nb < (size_t)NROWS) { issue8(nb, buf ^ 1); CP_WAIT1(); }
        else                    { CP_WAIT0(); }
        __syncwarp();

        u64 acc0[8], acc1[8];
#pragma unroll
        for (int rr = 0; rr < 8; ++rr) { acc0[rr] = 0; acc1[rr] = 0; }
#pragma unroll
        for (int k4 = 0; k4 < 16; ++k4) {
            const u64 w00 = w2p[2 * k4][j0];
            const u64 w01 = w2p[2 * k4 + 1][j0];
            const u64 w10 = w2p[2 * k4][j1];
            const u64 w11 = w2p[2 * k4 + 1][j1];
#pragma unroll
            for (int rr = 0; rr < 8; ++rr) {
                const ulonglong2 p =
                    ((const ulonglong2*)hst[buf][wid][rr])[k4];  // LDS.128 bcast
                acc0[rr] = fma2(w00, p.x, acc0[rr]);
                acc0[rr] = fma2(w01, p.y, acc0[rr]);
                acc1[rr] = fma2(w10, p.x, acc1[rr]);
                acc1[rr] = fma2(w11, p.y, acc1[rr]);
            }
        }

        // ---- LN epilogue, level-major interleaved across all 8 rows ----
        float o0[8], o1[8], s[8];
#pragma unroll
        for (int rr = 0; rr < 8; ++rr) {
            o0[rr] = psum(acc0[rr]) + bo0;
            o1[rr] = psum(acc1[rr]) + bo1;
            s[rr]  = o0[rr] + o1[rr];
        }
#pragma unroll
        for (int o = 16; o; o >>= 1)
#pragma unroll
            for (int rr = 0; rr < 8; ++rr)
                s[rr] += __shfl_xor_sync(0xffffffffu, s[rr], o);

        float d0[8], d1[8], q[8];
#pragma unroll
        for (int rr = 0; rr < 8; ++rr) {
            const float m = s[rr] * (1.f / 64.f);
            d0[rr] = o0[rr] - m;
            d1[rr] = o1[rr] - m;
            q[rr]  = d0[rr] * d0[rr] + d1[rr] * d1[rr];
        }
#pragma unroll
        for (int o = 16; o; o >>= 1)
#pragma unroll
            for (int rr = 0; rr < 8; ++rr)
                q[rr] += __shfl_xor_sync(0xffffffffu, q[rr], o);

#pragma unroll
        for (int rr = 0; rr < 8; ++rr) {
            const float rs = rsqrtf(q[rr] * (1.f / 64.f) + EPS);
            const size_t row = base + rr;
            out[row * DPK + j0] = d0[rr] * rs * lg0 + lb0;
            out[row * DPK + j1] = d1[rr] * rs * lg1 + lb1;
        }
        __syncwarp();   // all lanes done reading hst[buf] before it is refilled
    }
}

// ================== launcher =================================================
extern "C" void kernel_launch(void* const* d_in, const int* in_sizes, int n_in,
                              void* d_out, int out_size)
{
    const float* drug = (const float*)d_in[0];
    const float* w1   = (const float*)d_in[1];
    const float* b1   = (const float*)d_in[2];
    const float* ln1g = (const float*)d_in[3];
    const float* ln1b = (const float*)d_in[4];
    const float* Wih  = (const float*)d_in[5];
    const float* bih  = (const float*)d_in[6];
    const float* Whh  = (const float*)d_in[7];
    const float* bhh  = (const float*)d_in[8];
    const float* w2   = (const float*)d_in[9];
    const float* b2   = (const float*)d_in[10];
    const float* ln2g = (const float*)d_in[11];
    const float* ln2b = (const float*)d_in[12];
    float* out = (float*)d_out;

    k_inproj<<<NROWS / 8, 256>>>(drug, w1, b1, ln1g, ln1b);
    k_gru<<<BB / CH, 256>>>(Wih, bih, Whh, bhh);
    k_outproj<<<1024, 256>>>(w2, b2, ln2g, ln2b, out);
}